// round 4
// baseline (speedup 1.0000x reference)
#include <cuda_runtime.h>
#include <cstdint>

#define BSZ    4096
#define HEADS  4
#define HALF   256
#define NKEYS  512
#define KNN    32
#define VDIM   1024
#define INDIM  1024
#define QCOLS  2048      // HEADS * K_DIM = 4*512

// ---- scratch (device globals: allocation-free) ----
__device__ float g_q[(size_t)BSZ * QCOLS];               // 32 MB
__device__ float g_scores[(size_t)8 * BSZ * NKEYS];      // 64 MB : [hs][b][n]
__device__ float g_w[(size_t)BSZ * HEADS * KNN];         // 2 MB
__device__ int   g_idx[(size_t)BSZ * HEADS * KNN];       // 2 MB

// ---- packed f32x2 helpers (per-lane IEEE fp32; lane0 = low 32 bits) ----
__device__ __forceinline__ unsigned long long bcast2(float a) {
    unsigned long long d;
    uint32_t r = __float_as_uint(a);
    asm("mov.b64 %0, {%1, %1};" : "=l"(d) : "r"(r));
    return d;
}
__device__ __forceinline__ void fma2(unsigned long long& c,
                                     unsigned long long a, unsigned long long b) {
    asm("fma.rn.f32x2 %0, %1, %2, %0;" : "+l"(c) : "l"(a), "l"(b));
}
__device__ __forceinline__ float2 unpack2(unsigned long long v) {
    uint32_t lo, hi;
    asm("mov.b64 {%0, %1}, %2;" : "=r"(lo), "=r"(hi) : "l"(v));
    return make_float2(__uint_as_float(lo), __uint_as_float(hi));
}

// ============================================================================
// Kernel 1: q = x @ Wq   (M=4096, N=2048, K=1024)  NN, fp32 FFMA2
//   128x128 CTA tile, ktile 16, 256 threads, 8x8 per thread (4x2-packed).
//   Same FMA order per accumulator as the round-1 kernel -> identical results.
// ============================================================================
__global__ void __launch_bounds__(256) q_gemm(const float* __restrict__ A,
                                              const float* __restrict__ B) {
    const int N = QCOLS;
    const int K = INDIM;
    __shared__ float As[16][128];
    __shared__ float Bs[16][128];

    int tid = threadIdx.x;
    const float* Ab = A + (size_t)blockIdx.y * 128 * INDIM;
    const float* Bb = B + blockIdx.x * 128;

    unsigned long long acc2[8][4];
    #pragma unroll
    for (int i = 0; i < 8; i++)
        #pragma unroll
        for (int j = 0; j < 4; j++) acc2[i][j] = 0ull;

    int tx = (tid & 15) * 8;
    int ty = (tid >> 4) * 8;

    for (int k0 = 0; k0 < K; k0 += 16) {
        #pragma unroll
        for (int i = 0; i < 2; i++) {
            int idx = tid + i * 256;            // 0..511
            int row = idx >> 2;                 // 0..127
            int kq  = (idx & 3) * 4;            // 0,4,8,12
            float4 v = *(const float4*)(Ab + (size_t)row * INDIM + k0 + kq);
            As[kq + 0][row] = v.x; As[kq + 1][row] = v.y;
            As[kq + 2][row] = v.z; As[kq + 3][row] = v.w;
        }
        #pragma unroll
        for (int i = 0; i < 2; i++) {
            int idx = tid + i * 256;
            int kr = idx >> 5;                  // 0..15
            int cq = (idx & 31) * 4;            // 0..124
            *(float4*)&Bs[kr][cq] = *(const float4*)(Bb + (size_t)(k0 + kr) * N + cq);
        }
        __syncthreads();

        #pragma unroll
        for (int kk = 0; kk < 16; kk++) {
            float a[8];
            *(float4*)(a)     = *(float4*)&As[kk][ty];
            *(float4*)(a + 4) = *(float4*)&As[kk][ty + 4];
            ulonglong2 b01 = *(ulonglong2*)&Bs[kk][tx];      // cols tx..tx+3
            ulonglong2 b23 = *(ulonglong2*)&Bs[kk][tx + 4];  // cols tx+4..tx+7
            unsigned long long bp[4] = {b01.x, b01.y, b23.x, b23.y};
            #pragma unroll
            for (int i = 0; i < 8; i++) {
                unsigned long long ap = bcast2(a[i]);
                #pragma unroll
                for (int j = 0; j < 4; j++) fma2(acc2[i][j], ap, bp[j]);
            }
        }
        __syncthreads();
    }

    #pragma unroll
    for (int i = 0; i < 8; i++) {
        float2 c0 = unpack2(acc2[i][0]);
        float2 c1 = unpack2(acc2[i][1]);
        float2 c2 = unpack2(acc2[i][2]);
        float2 c3 = unpack2(acc2[i][3]);
        float* Cp = g_q + (size_t)(blockIdx.y * 128 + ty + i) * N + blockIdx.x * 128 + tx;
        *(float4*)(Cp)     = make_float4(c0.x, c0.y, c1.x, c1.y);
        *(float4*)(Cp + 4) = make_float4(c2.x, c2.y, c3.x, c3.y);
    }
}

// ============================================================================
// Kernel 2: scores[hs][b][n] = sum_d q[b, hs*256+d] * keys[hs][n][d]
//   NT gemm per hs: M=4096, N=512, K=256.  grid=(4, 32, 8).  fp32 FFMA2.
// ============================================================================
__global__ void __launch_bounds__(256) score_gemm(const float* __restrict__ keys) {
    const int hs = blockIdx.z;
    const float* Ab = g_q + hs * HALF + (size_t)blockIdx.y * 128 * QCOLS;
    const float* Bb = keys + (size_t)hs * NKEYS * HALF + (size_t)blockIdx.x * 128 * HALF;
    float* Cb = g_scores + (size_t)hs * BSZ * NKEYS;

    __shared__ float As[16][128];
    __shared__ float Bs[16][128];

    int tid = threadIdx.x;
    unsigned long long acc2[8][4];
    #pragma unroll
    for (int i = 0; i < 8; i++)
        #pragma unroll
        for (int j = 0; j < 4; j++) acc2[i][j] = 0ull;

    int tx = (tid & 15) * 8;
    int ty = (tid >> 4) * 8;

    for (int k0 = 0; k0 < HALF; k0 += 16) {
        #pragma unroll
        for (int i = 0; i < 2; i++) {
            int idx = tid + i * 256;
            int row = idx >> 2;
            int kq  = (idx & 3) * 4;
            float4 v = *(const float4*)(Ab + (size_t)row * QCOLS + k0 + kq);
            As[kq + 0][row] = v.x; As[kq + 1][row] = v.y;
            As[kq + 2][row] = v.z; As[kq + 3][row] = v.w;
        }
        #pragma unroll
        for (int i = 0; i < 2; i++) {
            int idx = tid + i * 256;
            int row = idx >> 2;
            int kq  = (idx & 3) * 4;
            float4 v = *(const float4*)(Bb + (size_t)row * HALF + k0 + kq);
            Bs[kq + 0][row] = v.x; Bs[kq + 1][row] = v.y;
            Bs[kq + 2][row] = v.z; Bs[kq + 3][row] = v.w;
        }
        __syncthreads();

        #pragma unroll
        for (int kk = 0; kk < 16; kk++) {
            float a[8];
            *(float4*)(a)     = *(float4*)&As[kk][ty];
            *(float4*)(a + 4) = *(float4*)&As[kk][ty + 4];
            ulonglong2 b01 = *(ulonglong2*)&Bs[kk][tx];
            ulonglong2 b23 = *(ulonglong2*)&Bs[kk][tx + 4];
            unsigned long long bp[4] = {b01.x, b01.y, b23.x, b23.y};
            #pragma unroll
            for (int i = 0; i < 8; i++) {
                unsigned long long ap = bcast2(a[i]);
                #pragma unroll
                for (int j = 0; j < 4; j++) fma2(acc2[i][j], ap, bp[j]);
            }
        }
        __syncthreads();
    }

    #pragma unroll
    for (int i = 0; i < 8; i++) {
        float2 c0 = unpack2(acc2[i][0]);
        float2 c1 = unpack2(acc2[i][1]);
        float2 c2 = unpack2(acc2[i][2]);
        float2 c3 = unpack2(acc2[i][3]);
        float* Cp = Cb + (size_t)(blockIdx.y * 128 + ty + i) * NKEYS + blockIdx.x * 128 + tx;
        *(float4*)(Cp)     = make_float4(c0.x, c0.y, c1.x, c1.y);
        *(float4*)(Cp + 4) = make_float4(c2.x, c2.y, c3.x, c3.y);
    }
}

// ============================================================================
// Kernel 3: per-(b,h) top-k + cartesian top-k + softmax (unchanged, proven)
// ============================================================================
__global__ void __launch_bounds__(128) topk_kernel() {
    const int b    = blockIdx.x;
    const int h    = threadIdx.x >> 5;
    const int lane = threadIdx.x & 31;

    __shared__ float sv[HEADS][2][KNN];
    __shared__ int   si[HEADS][2][KNN];
    __shared__ float sbest[HEADS][KNN];
    __shared__ int   sbf[HEADS][KNN];

    #pragma unroll
    for (int s = 0; s < 2; s++) {
        const float* p = g_scores + ((size_t)(h * 2 + s)) * BSZ * NKEYS + (size_t)b * NKEYS;
        float v[16];
        #pragma unroll
        for (int j = 0; j < 16; j++) v[j] = p[j * 32 + lane];

        for (int r = 0; r < KNN; r++) {
            float bv = -1e30f; int bi = 1 << 30;
            #pragma unroll
            for (int j = 0; j < 16; j++) {
                if (v[j] > bv) { bv = v[j]; bi = j * 32 + lane; }
            }
            #pragma unroll
            for (int off = 16; off; off >>= 1) {
                float ov = __shfl_xor_sync(0xffffffffu, bv, off);
                int   oi = __shfl_xor_sync(0xffffffffu, bi, off);
                if (ov > bv || (ov == bv && oi < bi)) { bv = ov; bi = oi; }
            }
            if ((bi & 31) == lane) {
                int rem = bi >> 5;
                #pragma unroll
                for (int j = 0; j < 16; j++) if (j == rem) v[j] = -1e30f;
            }
            if (lane == 0) { sv[h][s][r] = bv; si[h][s][r] = bi; }
        }
    }
    __syncwarp();

    float cv[KNN];
    float s1l = sv[h][0][lane];
    #pragma unroll
    for (int j = 0; j < KNN; j++) cv[j] = s1l + sv[h][1][j];

    for (int r = 0; r < KNN; r++) {
        float bv = -1e30f; int bf = 1 << 30;
        #pragma unroll
        for (int j = 0; j < KNN; j++) {
            if (cv[j] > bv) { bv = cv[j]; bf = lane * 32 + j; }
        }
        #pragma unroll
        for (int off = 16; off; off >>= 1) {
            float ov = __shfl_xor_sync(0xffffffffu, bv, off);
            int   oi = __shfl_xor_sync(0xffffffffu, bf, off);
            if (ov > bv || (ov == bv && oi < bf)) { bv = ov; bf = oi; }
        }
        if ((bf >> 5) == lane) {
            int rem = bf & 31;
            #pragma unroll
            for (int j = 0; j < KNN; j++) if (j == rem) cv[j] = -1e30f;
        }
        if (lane == 0) { sbest[h][r] = bv; sbf[h][r] = bf; }
    }
    __syncwarp();

    float m = sbest[h][0];
    float e = expf(sbest[h][lane] - m);
    float sum = e;
    #pragma unroll
    for (int off = 16; off; off >>= 1) sum += __shfl_xor_sync(0xffffffffu, sum, off);
    float wgt = e / sum;

    int f = sbf[h][lane];
    int index = si[h][0][f >> 5] * NKEYS + si[h][1][f & 31];

    g_w  [(size_t)(b * HEADS + h) * KNN + lane] = wgt;
    g_idx[(size_t)(b * HEADS + h) * KNN + lane] = index;
}

// ============================================================================
// Kernel 4: gather + weighted sum (89.4% DRAM — at roofline, unchanged)
// ============================================================================
__global__ void __launch_bounds__(256) gather_kernel(const float* __restrict__ values,
                                                     float* __restrict__ out) {
    const int b = blockIdx.x;
    const int t = threadIdx.x;
    __shared__ float ws[HEADS * KNN];
    __shared__ int   is[HEADS * KNN];
    if (t < HEADS * KNN) {
        ws[t] = g_w[(size_t)b * HEADS * KNN + t];
        is[t] = g_idx[(size_t)b * HEADS * KNN + t];
    }
    __syncthreads();

    const float4* V = (const float4*)values;
    float4 acc = make_float4(0.f, 0.f, 0.f, 0.f);

    #pragma unroll 8
    for (int k = 0; k < HEADS * KNN; k++) {
        float w = ws[k];
        size_t row = (size_t)is[k];
        float4 v = V[row * (VDIM / 4) + t];
        acc.x += w * v.x; acc.y += w * v.y;
        acc.z += w * v.z; acc.w += w * v.w;
    }
    ((float4*)out)[(size_t)b * (VDIM / 4) + t] = acc;
}

// ============================================================================
extern "C" void kernel_launch(void* const* d_in, const int* in_sizes, int n_in,
                              void* d_out, int out_size) {
    const float* x      = (const float*)d_in[0];   // (4096, 1024)
    const float* wq     = (const float*)d_in[1];   // (1024, 2048)
    const float* keys   = (const float*)d_in[2];   // (4, 2, 512, 256)
    const float* values = (const float*)d_in[3];   // (262144, 1024)
    float* out = (float*)d_out;                    // (4096, 1024)

    {
        dim3 grid(QCOLS / 128, BSZ / 128);  // (16, 32)
        q_gemm<<<grid, 256>>>(x, wq);
    }
    {
        dim3 grid(NKEYS / 128, BSZ / 128, 8);  // (4, 32, 8)
        score_gemm<<<grid, 256>>>(keys);
    }
    topk_kernel<<<BSZ, 128>>>();
    gather_kernel<<<BSZ, 256>>>(values, out);
}

// round 5
// speedup vs baseline: 1.0974x; 1.0974x over previous
#include <cuda_runtime.h>
#include <cstdint>

#define BSZ    4096
#define HEADS  4
#define HALF   256
#define NKEYS  512
#define KNN    32
#define VDIM   1024
#define INDIM  1024
#define QCOLS  2048      // HEADS * K_DIM = 4*512

// ---- scratch (device globals: allocation-free) ----
__device__ float g_q[(size_t)BSZ * QCOLS];               // 32 MB
__device__ float g_scores[(size_t)8 * BSZ * NKEYS];      // 64 MB : [hs][b][n]
__device__ float g_w[(size_t)BSZ * HEADS * KNN];         // 2 MB
__device__ int   g_idx[(size_t)BSZ * HEADS * KNN];       // 2 MB

// ============================================================================
// Kernel 1: q = x @ Wq   (M=4096, N=2048, K=1024)  NN, fp32, 128x128x16 tiles
//   Double-buffered smem + register prefetch; one barrier per k-tile.
//   Accumulation order identical to the round-1 kernel (bit-identical output).
// ============================================================================
__global__ void __launch_bounds__(256, 2) q_gemm(const float* __restrict__ A,
                                                 const float* __restrict__ B) {
    const int N = QCOLS;
    const int K = INDIM;
    __shared__ float As[2][16][128];
    __shared__ float Bs[2][16][128];

    const int tid = threadIdx.x;
    const float* Ab = A + (size_t)blockIdx.y * 128 * INDIM;
    const float* Bb = B + blockIdx.x * 128;

    // per-thread load coordinates (2 float4 each for A and B)
    const int a_row0 = tid >> 2;                 // 0..63
    const int a_row1 = a_row0 + 64;
    const int a_kq   = (tid & 3) * 4;            // 0,4,8,12
    const int b_kr0  = tid >> 5;                 // 0..7
    const int b_kr1  = b_kr0 + 8;
    const int b_cq   = (tid & 31) * 4;           // 0..124

    float acc[8][8];
    #pragma unroll
    for (int i = 0; i < 8; i++)
        #pragma unroll
        for (int j = 0; j < 8; j++) acc[i][j] = 0.f;

    const int tx = (tid & 15) * 8;
    const int ty = (tid >> 4) * 8;

    float4 ra0, ra1, rb0, rb1;

    // prologue: tile 0 -> regs -> smem[0]
    ra0 = *(const float4*)(Ab + (size_t)a_row0 * INDIM + a_kq);
    ra1 = *(const float4*)(Ab + (size_t)a_row1 * INDIM + a_kq);
    rb0 = *(const float4*)(Bb + (size_t)b_kr0 * N + b_cq);
    rb1 = *(const float4*)(Bb + (size_t)b_kr1 * N + b_cq);
    As[0][a_kq + 0][a_row0] = ra0.x; As[0][a_kq + 1][a_row0] = ra0.y;
    As[0][a_kq + 2][a_row0] = ra0.z; As[0][a_kq + 3][a_row0] = ra0.w;
    As[0][a_kq + 0][a_row1] = ra1.x; As[0][a_kq + 1][a_row1] = ra1.y;
    As[0][a_kq + 2][a_row1] = ra1.z; As[0][a_kq + 3][a_row1] = ra1.w;
    *(float4*)&Bs[0][b_kr0][b_cq] = rb0;
    *(float4*)&Bs[0][b_kr1][b_cq] = rb1;
    __syncthreads();

    const int ntiles = K / 16;
    for (int t = 0; t < ntiles; t++) {
        const int cur = t & 1;
        if (t + 1 < ntiles) {
            const int k0 = (t + 1) * 16;
            ra0 = *(const float4*)(Ab + (size_t)a_row0 * INDIM + k0 + a_kq);
            ra1 = *(const float4*)(Ab + (size_t)a_row1 * INDIM + k0 + a_kq);
            rb0 = *(const float4*)(Bb + (size_t)(k0 + b_kr0) * N + b_cq);
            rb1 = *(const float4*)(Bb + (size_t)(k0 + b_kr1) * N + b_cq);
        }

        #pragma unroll
        for (int kk = 0; kk < 16; kk++) {
            float a[8], b[8];
            *(float4*)(a)     = *(float4*)&As[cur][kk][ty];
            *(float4*)(a + 4) = *(float4*)&As[cur][kk][ty + 4];
            *(float4*)(b)     = *(float4*)&Bs[cur][kk][tx];
            *(float4*)(b + 4) = *(float4*)&Bs[cur][kk][tx + 4];
            #pragma unroll
            for (int i = 0; i < 8; i++)
                #pragma unroll
                for (int j = 0; j < 8; j++) acc[i][j] += a[i] * b[j];
        }

        if (t + 1 < ntiles) {
            const int nxt = cur ^ 1;
            As[nxt][a_kq + 0][a_row0] = ra0.x; As[nxt][a_kq + 1][a_row0] = ra0.y;
            As[nxt][a_kq + 2][a_row0] = ra0.z; As[nxt][a_kq + 3][a_row0] = ra0.w;
            As[nxt][a_kq + 0][a_row1] = ra1.x; As[nxt][a_kq + 1][a_row1] = ra1.y;
            As[nxt][a_kq + 2][a_row1] = ra1.z; As[nxt][a_kq + 3][a_row1] = ra1.w;
            *(float4*)&Bs[nxt][b_kr0][b_cq] = rb0;
            *(float4*)&Bs[nxt][b_kr1][b_cq] = rb1;
            __syncthreads();
        }
    }

    #pragma unroll
    for (int i = 0; i < 8; i++) {
        float* Cp = g_q + (size_t)(blockIdx.y * 128 + ty + i) * N + blockIdx.x * 128 + tx;
        *(float4*)(Cp)     = make_float4(acc[i][0], acc[i][1], acc[i][2], acc[i][3]);
        *(float4*)(Cp + 4) = make_float4(acc[i][4], acc[i][5], acc[i][6], acc[i][7]);
    }
}

// ============================================================================
// Kernel 2: scores[hs][b][n] = sum_d q[b, hs*256+d] * keys[hs][n][d]
//   NT gemm per hs: M=4096, N=512, K=256.  grid=(4, 32, 8).
//   Same double-buffered pipeline; identical accumulation order to round 1.
// ============================================================================
__global__ void __launch_bounds__(256, 2) score_gemm(const float* __restrict__ keys) {
    const int hs = blockIdx.z;
    const float* Ab = g_q + hs * HALF + (size_t)blockIdx.y * 128 * QCOLS;
    const float* Bb = keys + (size_t)hs * NKEYS * HALF + (size_t)blockIdx.x * 128 * HALF;
    float* Cb = g_scores + (size_t)hs * BSZ * NKEYS;

    __shared__ float As[2][16][128];
    __shared__ float Bs[2][16][128];

    const int tid = threadIdx.x;
    const int a_row0 = tid >> 2;
    const int a_row1 = a_row0 + 64;
    const int a_kq   = (tid & 3) * 4;

    float acc[8][8];
    #pragma unroll
    for (int i = 0; i < 8; i++)
        #pragma unroll
        for (int j = 0; j < 8; j++) acc[i][j] = 0.f;

    const int tx = (tid & 15) * 8;
    const int ty = (tid >> 4) * 8;

    float4 ra0, ra1, rb0, rb1;

    ra0 = *(const float4*)(Ab + (size_t)a_row0 * QCOLS + a_kq);
    ra1 = *(const float4*)(Ab + (size_t)a_row1 * QCOLS + a_kq);
    rb0 = *(const float4*)(Bb + (size_t)a_row0 * HALF + a_kq);
    rb1 = *(const float4*)(Bb + (size_t)a_row1 * HALF + a_kq);
    As[0][a_kq + 0][a_row0] = ra0.x; As[0][a_kq + 1][a_row0] = ra0.y;
    As[0][a_kq + 2][a_row0] = ra0.z; As[0][a_kq + 3][a_row0] = ra0.w;
    As[0][a_kq + 0][a_row1] = ra1.x; As[0][a_kq + 1][a_row1] = ra1.y;
    As[0][a_kq + 2][a_row1] = ra1.z; As[0][a_kq + 3][a_row1] = ra1.w;
    Bs[0][a_kq + 0][a_row0] = rb0.x; Bs[0][a_kq + 1][a_row0] = rb0.y;
    Bs[0][a_kq + 2][a_row0] = rb0.z; Bs[0][a_kq + 3][a_row0] = rb0.w;
    Bs[0][a_kq + 0][a_row1] = rb1.x; Bs[0][a_kq + 1][a_row1] = rb1.y;
    Bs[0][a_kq + 2][a_row1] = rb1.z; Bs[0][a_kq + 3][a_row1] = rb1.w;
    __syncthreads();

    const int ntiles = HALF / 16;
    for (int t = 0; t < ntiles; t++) {
        const int cur = t & 1;
        if (t + 1 < ntiles) {
            const int k0 = (t + 1) * 16;
            ra0 = *(const float4*)(Ab + (size_t)a_row0 * QCOLS + k0 + a_kq);
            ra1 = *(const float4*)(Ab + (size_t)a_row1 * QCOLS + k0 + a_kq);
            rb0 = *(const float4*)(Bb + (size_t)a_row0 * HALF + k0 + a_kq);
            rb1 = *(const float4*)(Bb + (size_t)a_row1 * HALF + k0 + a_kq);
        }

        #pragma unroll
        for (int kk = 0; kk < 16; kk++) {
            float a[8], b[8];
            *(float4*)(a)     = *(float4*)&As[cur][kk][ty];
            *(float4*)(a + 4) = *(float4*)&As[cur][kk][ty + 4];
            *(float4*)(b)     = *(float4*)&Bs[cur][kk][tx];
            *(float4*)(b + 4) = *(float4*)&Bs[cur][kk][tx + 4];
            #pragma unroll
            for (int i = 0; i < 8; i++)
                #pragma unroll
                for (int j = 0; j < 8; j++) acc[i][j] += a[i] * b[j];
        }

        if (t + 1 < ntiles) {
            const int nxt = cur ^ 1;
            As[nxt][a_kq + 0][a_row0] = ra0.x; As[nxt][a_kq + 1][a_row0] = ra0.y;
            As[nxt][a_kq + 2][a_row0] = ra0.z; As[nxt][a_kq + 3][a_row0] = ra0.w;
            As[nxt][a_kq + 0][a_row1] = ra1.x; As[nxt][a_kq + 1][a_row1] = ra1.y;
            As[nxt][a_kq + 2][a_row1] = ra1.z; As[nxt][a_kq + 3][a_row1] = ra1.w;
            Bs[nxt][a_kq + 0][a_row0] = rb0.x; Bs[nxt][a_kq + 1][a_row0] = rb0.y;
            Bs[nxt][a_kq + 2][a_row0] = rb0.z; Bs[nxt][a_kq + 3][a_row0] = rb0.w;
            Bs[nxt][a_kq + 0][a_row1] = rb1.x; Bs[nxt][a_kq + 1][a_row1] = rb1.y;
            Bs[nxt][a_kq + 2][a_row1] = rb1.z; Bs[nxt][a_kq + 3][a_row1] = rb1.w;
            __syncthreads();
        }
    }

    #pragma unroll
    for (int i = 0; i < 8; i++) {
        float* Cp = Cb + (size_t)(blockIdx.y * 128 + ty + i) * NKEYS + blockIdx.x * 128 + tx;
        *(float4*)(Cp)     = make_float4(acc[i][0], acc[i][1], acc[i][2], acc[i][3]);
        *(float4*)(Cp + 4) = make_float4(acc[i][4], acc[i][5], acc[i][6], acc[i][7]);
    }
}

// ============================================================================
// Kernel 3: per-(b,h) top-k + cartesian top-k + softmax (proven, unchanged)
// ============================================================================
__global__ void __launch_bounds__(128) topk_kernel() {
    const int b    = blockIdx.x;
    const int h    = threadIdx.x >> 5;
    const int lane = threadIdx.x & 31;

    __shared__ float sv[HEADS][2][KNN];
    __shared__ int   si[HEADS][2][KNN];
    __shared__ float sbest[HEADS][KNN];
    __shared__ int   sbf[HEADS][KNN];

    #pragma unroll
    for (int s = 0; s < 2; s++) {
        const float* p = g_scores + ((size_t)(h * 2 + s)) * BSZ * NKEYS + (size_t)b * NKEYS;
        float v[16];
        #pragma unroll
        for (int j = 0; j < 16; j++) v[j] = p[j * 32 + lane];

        for (int r = 0; r < KNN; r++) {
            float bv = -1e30f; int bi = 1 << 30;
            #pragma unroll
            for (int j = 0; j < 16; j++) {
                if (v[j] > bv) { bv = v[j]; bi = j * 32 + lane; }
            }
            #pragma unroll
            for (int off = 16; off; off >>= 1) {
                float ov = __shfl_xor_sync(0xffffffffu, bv, off);
                int   oi = __shfl_xor_sync(0xffffffffu, bi, off);
                if (ov > bv || (ov == bv && oi < bi)) { bv = ov; bi = oi; }
            }
            if ((bi & 31) == lane) {
                int rem = bi >> 5;
                #pragma unroll
                for (int j = 0; j < 16; j++) if (j == rem) v[j] = -1e30f;
            }
            if (lane == 0) { sv[h][s][r] = bv; si[h][s][r] = bi; }
        }
    }
    __syncwarp();

    float cv[KNN];
    float s1l = sv[h][0][lane];
    #pragma unroll
    for (int j = 0; j < KNN; j++) cv[j] = s1l + sv[h][1][j];

    for (int r = 0; r < KNN; r++) {
        float bv = -1e30f; int bf = 1 << 30;
        #pragma unroll
        for (int j = 0; j < KNN; j++) {
            if (cv[j] > bv) { bv = cv[j]; bf = lane * 32 + j; }
        }
        #pragma unroll
        for (int off = 16; off; off >>= 1) {
            float ov = __shfl_xor_sync(0xffffffffu, bv, off);
            int   oi = __shfl_xor_sync(0xffffffffu, bf, off);
            if (ov > bv || (ov == bv && oi < bf)) { bv = ov; bf = oi; }
        }
        if ((bf >> 5) == lane) {
            int rem = bf & 31;
            #pragma unroll
            for (int j = 0; j < KNN; j++) if (j == rem) cv[j] = -1e30f;
        }
        if (lane == 0) { sbest[h][r] = bv; sbf[h][r] = bf; }
    }
    __syncwarp();

    float m = sbest[h][0];
    float e = expf(sbest[h][lane] - m);
    float sum = e;
    #pragma unroll
    for (int off = 16; off; off >>= 1) sum += __shfl_xor_sync(0xffffffffu, sum, off);
    float wgt = e / sum;

    int f = sbf[h][lane];
    int index = si[h][0][f >> 5] * NKEYS + si[h][1][f & 31];

    g_w  [(size_t)(b * HEADS + h) * KNN + lane] = wgt;
    g_idx[(size_t)(b * HEADS + h) * KNN + lane] = index;
}

// ============================================================================
// Kernel 4: gather + weighted sum (87-89% DRAM — at roofline, unchanged)
// ============================================================================
__global__ void __launch_bounds__(256) gather_kernel(const float* __restrict__ values,
                                                     float* __restrict__ out) {
    const int b = blockIdx.x;
    const int t = threadIdx.x;
    __shared__ float ws[HEADS * KNN];
    __shared__ int   is[HEADS * KNN];
    if (t < HEADS * KNN) {
        ws[t] = g_w[(size_t)b * HEADS * KNN + t];
        is[t] = g_idx[(size_t)b * HEADS * KNN + t];
    }
    __syncthreads();

    const float4* V = (const float4*)values;
    float4 acc = make_float4(0.f, 0.f, 0.f, 0.f);

    #pragma unroll 8
    for (int k = 0; k < HEADS * KNN; k++) {
        float w = ws[k];
        size_t row = (size_t)is[k];
        float4 v = V[row * (VDIM / 4) + t];
        acc.x += w * v.x; acc.y += w * v.y;
        acc.z += w * v.z; acc.w += w * v.w;
    }
    ((float4*)out)[(size_t)b * (VDIM / 4) + t] = acc;
}

// ============================================================================
extern "C" void kernel_launch(void* const* d_in, const int* in_sizes, int n_in,
                              void* d_out, int out_size) {
    const float* x      = (const float*)d_in[0];   // (4096, 1024)
    const float* wq     = (const float*)d_in[1];   // (1024, 2048)
    const float* keys   = (const float*)d_in[2];   // (4, 2, 512, 256)
    const float* values = (const float*)d_in[3];   // (262144, 1024)
    float* out = (float*)d_out;                    // (4096, 1024)

    {
        dim3 grid(QCOLS / 128, BSZ / 128);  // (16, 32)
        q_gemm<<<grid, 256>>>(x, wq);
    }
    {
        dim3 grid(NKEYS / 128, BSZ / 128, 8);  // (4, 32, 8)
        score_gemm<<<grid, 256>>>(keys);
    }
    topk_kernel<<<BSZ, 128>>>();
    gather_kernel<<<BSZ, 256>>>(values, out);
}